// round 7
// baseline (speedup 1.0000x reference)
#include <cuda_runtime.h>

// ---------------- problem constants ----------------
#define NB 4
#define NC 512
#define NG 2048
#define CH 3
#define NP 3
#define NBAS 10
#define OC 64
#define EPSF 1e-6f
#define BNEPS 1e-5f
#define LOG2E_F 1.4426950408889634f
#define PI2F 6.283185307179586f
#define INV2PI_F 0.15915494309189535f
#define PI2_D 6.2831853071795864769
#define SQRT_2_OVER_NBAS 0.4472135954999579f

#define ELEMS (NB * NG * CH * NP)  // 73728
#define NBIN 1024
#define RFACT 15.0f                // window radius = 15*scale (> 13.22 ftz-zero bound)

#define NBLK 768                   // all co-resident (launch_bounds(256,6) -> 888 slots)
#define NTHR 256

#define SORT_BLKS 96               // 8 blocks per (b,c), 64 elements each
#define BIN_BLKS 12

#define FG 16
#define FTILES (NB * (NG / FG))    // 512
#define HALO 4
#define FGH (FG + 2 * HALO)        // 24
#define FCONV (9 * FG)             // 144
#define K5P ((NB * NG) / FTILES)   // 16

// output offsets (flattened tuple concat: y_out, n_f, fourier, n_h1, h0_f)
#define OFF_NF  (NB * NG * OC)
#define OFF_FP  (OFF_NF + ELEMS)
#define OFF_NH1 (OFF_FP + ELEMS)
#define OFF_H0  (OFF_NH1 + ELEMS)

// ---------------- scratch (no allocs allowed) ----------------
__device__ float2 g_ctx[NB * CH * NC];   // context (x,y) sorted by x per (b,c)
__device__ float  g_gbx[NB * CH * NG];   // grid x, value-binned per (b,c)
__device__ int    g_gbi[NB * CH * NG];   // original grid index per binned slot
__device__ float  g_ph0[ELEMS];
__device__ float  g_ph1[ELEMS];
__device__ float  g_conv[ELEMS];
__device__ float  g_psum[9 * FTILES];
__device__ float  g_psq [9 * FTILES];
__device__ unsigned g_bar  = 0;          // monotonic grid barrier counter
__device__ unsigned g_exit = 0;          // exit counter (resets g_bar per replay)

// ---------------- shared memory union (phases are sequential) ----------------
struct ShSort { unsigned key[NC]; float x[NC]; float y[NC]; int pr[8 * 32]; };
struct ShBin  { int hist[NBIN]; int ofs[NBIN]; int ss[NTHR]; };
struct ShK1   { float2 sctx[NC]; float sxv[32]; int sgi[32]; float sacc[8 * 6 * 32]; };
struct ShF    { float spos[FGH * 9]; float ssw[NBAS * 3]; float ssb[NBAS * 3];
                float srw[NBAS]; float sgw[OC * 19]; float sgb2[OC];
                float sA[9]; float sB[9]; float feat[K5P * 18]; };
union ShU { ShSort srt; ShBin bn; ShK1 k1; ShF f; };

__device__ __forceinline__ float ex2f(float x) {
    float y;
    asm("ex2.approx.ftz.f32 %0, %1;" : "=f"(y) : "f"(x));
    return y;
}

// fp32 Cody-Waite cos reduction (no FP64), abs err ~7e-7 for |arg| up to ~2e5
__device__ __forceinline__ float cos_red(float arg) {
    const float F2PI     = (float)PI2_D;
    const float F2PI_RES = (float)(PI2_D - (double)((float)PI2_D));
    float n = rintf(arg * INV2PI_F);
    float r = fmaf(-n, F2PI, arg);
    r = fmaf(-n, F2PI_RES, r);
    return __cosf(r);
}

// grid-wide spin barrier; target = k * NBLK for the k-th barrier (monotonic counter)
__device__ __forceinline__ void grid_bar(unsigned target) {
    __syncthreads();
    __threadfence();
    if (threadIdx.x == 0) {
        atomicAdd(&g_bar, 1u);
        while (atomicAdd(&g_bar, 0u) < target) __nanosleep(64);
    }
    __syncthreads();
    __threadfence();   // gpu-scope: invalidates L1 so post-barrier loads see peer writes
}

// ======================= THE kernel =======================
__global__ __launch_bounds__(NTHR, 6) void k_all(
    const float* __restrict__ x_c, const float* __restrict__ y_c,
    const float* __restrict__ x_g, const float* __restrict__ sigma,
    const float* __restrict__ mu,  const float* __restrict__ eps1,
    const float* __restrict__ b_u, const float* __restrict__ rw,
    const float* __restrict__ w1, const float* __restrict__ b1,
    const float* __restrict__ w2, const float* __restrict__ b2,
    const float* __restrict__ w3, const float* __restrict__ b3,
    const float* __restrict__ gamma, const float* __restrict__ beta,
    const float* __restrict__ gw,    const float* __restrict__ gb,
    float* __restrict__ out)
{
    __shared__ ShU sh;
    const int unit = blockIdx.x;
    const int tid  = threadIdx.x;

    // ================= Phase 0: prep =================
    if (unit < SORT_BLKS) {
        // rank sort of context per (b,c): 8 blocks/(b,c), 64 elements each.
        // warp = (elem-group of 32) x (j-quarter of 128); deterministic tie-break by index.
        int bc = unit >> 3;
        int part = unit & 7;
        int b = bc / 3, c = bc % 3;
        for (int i = tid; i < NC; i += NTHR) {
            float xv = x_c[(b * NC + i) * CH + c];
            int f = __float_as_int(xv);
            sh.srt.key[i] = (f < 0) ? ~(unsigned)f : ((unsigned)f | 0x80000000u);
            sh.srt.x[i] = xv;
            sh.srt.y[i] = y_c[(b * NC + i) * CH + c];
        }
        __syncthreads();
        {
            int wq = tid >> 5, lane = tid & 31;
            int grp = wq >> 2, jq = wq & 3;
            int e = part * 64 + grp * 32 + lane;
            unsigned ki = sh.srt.key[e];
            int r = 0;
            int j0 = jq * (NC / 4);
#pragma unroll 8
            for (int j = j0; j < j0 + NC / 4; j++) {
                unsigned kj = sh.srt.key[j];
                r += (kj < ki) ? 1 : 0;
                r += (kj == ki && j < e) ? 1 : 0;
            }
            sh.srt.pr[wq * 32 + lane] = r;
        }
        __syncthreads();
        if (tid < 64) {
            int grp2 = tid >> 5, l2 = tid & 31;
            int rank = sh.srt.pr[(grp2 * 4 + 0) * 32 + l2]
                     + sh.srt.pr[(grp2 * 4 + 1) * 32 + l2]
                     + sh.srt.pr[(grp2 * 4 + 2) * 32 + l2]
                     + sh.srt.pr[(grp2 * 4 + 3) * 32 + l2];
            int e2 = part * 64 + tid;
            g_ctx[bc * NC + rank] = make_float2(sh.srt.x[e2], sh.srt.y[e2]);
        }
    } else if (unit < SORT_BLKS + BIN_BLKS) {
        // value-bin grid per (b,c). Bin-internal order is nondeterministic but
        // provably does not change any output bit (edge points have exact-zero
        // ftz weights; each lane's own 13.2s window is always fully covered).
        int u = unit - SORT_BLKS;
        int b = u / 3, c = u % 3;
        for (int i = tid; i < NBIN; i += NTHR) sh.bn.hist[i] = 0;
        __syncthreads();
        for (int i = tid; i < NG; i += NTHR) {
            float xv = x_g[(b * NG + i) * CH + c];
            int bin = (int)((xv + 5.0f) * (NBIN / 10.0f));
            bin = min(max(bin, 0), NBIN - 1);
            atomicAdd(&sh.bn.hist[bin], 1);
        }
        __syncthreads();
        int b4 = 4 * tid;
        int h0v = sh.bn.hist[b4], h1v = sh.bn.hist[b4 + 1];
        int h2v = sh.bn.hist[b4 + 2], h3v = sh.bn.hist[b4 + 3];
        sh.bn.ss[tid] = h0v + h1v + h2v + h3v;
        __syncthreads();
        for (int d = 1; d < NTHR; d <<= 1) {
            int v = sh.bn.ss[tid];
            int w2 = (tid >= d) ? sh.bn.ss[tid - d] : 0;
            __syncthreads();
            sh.bn.ss[tid] = v + w2;
            __syncthreads();
        }
        int excl = tid ? sh.bn.ss[tid - 1] : 0;
        sh.bn.ofs[b4]     = excl;
        sh.bn.ofs[b4 + 1] = excl + h0v;
        sh.bn.ofs[b4 + 2] = excl + h0v + h1v;
        sh.bn.ofs[b4 + 3] = excl + h0v + h1v + h2v;
        __syncthreads();
        for (int i = tid; i < NG; i += NTHR) {
            float xv = x_g[(b * NG + i) * CH + c];
            int bin = (int)((xv + 5.0f) * (NBIN / 10.0f));
            bin = min(max(bin, 0), NBIN - 1);
            int p = atomicAdd(&sh.bn.ofs[bin], 1);
            g_gbx[(b * CH + c) * NG + p] = xv;
            g_gbi[(b * CH + c) * NG + p] = i;
        }
    }

    grid_bar(1u * NBLK);

    // ================= Phase 1: windowed RBF sums =================
    // Block = (b, c, tile of 32 value-adjacent grid pts). 8 warps cover fixed
    // context chunks {w, w+8, w+16, w+24} (16 pts each) intersected with the
    // warp's per-p window. Fixed chunks + fixed combine order => deterministic.
    {
        int gt = unit % (NG / 32);
        int c  = (unit / (NG / 32)) % CH;
        int b  = unit / ((NG / 32) * CH);
        int lane = tid & 31, w = tid >> 5;

        const float2* ctx = g_ctx + (b * CH + c) * NC;
        for (int i = tid; i < NC; i += NTHR) sh.k1.sctx[i] = ctx[i];
        if (tid < 32) {
            sh.k1.sxv[tid] = g_gbx[(b * CH + c) * NG + gt * 32 + tid];
            sh.k1.sgi[tid] = g_gbi[(b * CH + c) * NG + gt * 32 + tid];
        }
        __syncthreads();

        float xg = sh.k1.sxv[lane];
        float lo = xg, hi = xg;
#pragma unroll
        for (int st = 16; st; st >>= 1) {
            lo = fminf(lo, __shfl_xor_sync(0xffffffffu, lo, st));
            hi = fmaxf(hi, __shfl_xor_sync(0xffffffffu, hi, st));
        }

        float ks[3], rr[3];
#pragma unroll
        for (int p = 0; p < 3; p++) {
            float s = expf(sigma[p]) + EPSF;
            ks[p] = -0.5f * LOG2E_F / (s * s);
            rr[p] = RFACT * s;
        }

#pragma unroll
        for (int p = 0; p < 3; p++) {
            float vlo = lo - rr[p], vhi = hi + rr[p];
            int i0, i1;
            { int l = 0, h = NC; while (l < h) { int m = (l + h) >> 1; if (sh.k1.sctx[m].x < vlo) l = m + 1; else h = m; } i0 = l; }
            { int l = 0, h = NC; while (l < h) { int m = (l + h) >> 1; if (sh.k1.sctx[m].x < vhi) l = m + 1; else h = m; } i1 = l; }
            float kp = ks[p];
            float a0 = 0.f, a1 = 0.f;
#pragma unroll
            for (int cc = 0; cc < 4; cc++) {
                int ci = w + cc * 8;
                int a  = max(i0, ci * 16);
                int bb = min(i1, ci * 16 + 16);
#pragma unroll 2
                for (int i = a; i < bb; i++) {
                    float2 cy = sh.k1.sctx[i];
                    float d = xg - cy.x;
                    float wv = ex2f(d * d * kp);
                    a0 += wv;
                    a1 = fmaf(wv, cy.y, a1);
                }
            }
            sh.k1.sacc[(w * 6 + p * 2 + 0) * 32 + lane] = a0;
            sh.k1.sacc[(w * 6 + p * 2 + 1) * 32 + lane] = a1;
        }
        __syncthreads();

        if (tid < 192) {
            int j = tid >> 5;
            int l = tid & 31;
            float v = 0.f;
#pragma unroll
            for (int s = 0; s < 8; s++) v += sh.k1.sacc[(s * 6 + j) * 32 + l];
            int p = j >> 1;
            int base = ((b * NG + sh.k1.sgi[l]) * CH + c) * NP + p;
            if ((j & 1) == 0) g_ph0[base] = v;
            else              g_ph1[base] = v;
        }
    }

    grid_bar(2u * NBLK);

    // ================= Phase 2: combine + Fourier + conv + BN partials =================
    int fb = unit / (NG / FG);   // batch for tiles (valid when unit < FTILES)
    int fg0 = (unit % (NG / FG)) * FG;

    if (unit < FTILES) {
        if (tid < NBAS * 3) {
            int k = tid / 3, p = tid % 3;
            float wmu  = expf(mu[p]);
            float wstd = 1.0f / (expf(sigma[p]) + EPSF);
            float e = eps1[(fb * NBAS + k) * NP + p];
            float u = b_u [(fb * NBAS + k) * NP + p];
            sh.f.ssw[tid] = __fadd_rn(wmu, __fmul_rn(wstd, e));
            sh.f.ssb[tid] = __fmul_rn(PI2F, u);
        }
        if (tid < NBAS) sh.f.srw[tid] = rw[tid];
        __syncthreads();

        if (tid < FGH * 9) {
            int jj = tid / 9;
            int cp = tid % 9;
            int c = cp / 3, p = cp % 3;
            int g = fg0 - HALO + jj;
            float pos = 0.f;
            if (g >= 0 && g < NG) {
                int idx = ((fb * NG + g) * CH + c) * NP + p;
                float h0 = g_ph0[idx];
                float h1 = g_ph1[idx];
                float nh1 = h1 / (h0 + EPSF);

                float xg = x_g[(fb * NG + g) * CH + c];
                float acc = 0.f;
#pragma unroll
                for (int k = 0; k < NBAS; k++) {
                    float arg = __fadd_rn(__fmul_rn(sh.f.ssw[k * 3 + p], xg), sh.f.ssb[k * 3 + p]);
                    acc = __fadd_rn(acc, __fmul_rn(sh.f.srw[k], cos_red(arg)));
                }
                float fp = SQRT_2_OVER_NBAS * acc;
                pos = nh1 + fp;

                if (jj >= HALO && jj < HALO + FG) {
                    out[OFF_NH1 + idx] = nh1;
                    out[OFF_FP  + idx] = fp;
                    out[OFF_H0  + idx] = h0;
                }
            }
            sh.f.spos[tid] = pos;
        }
        __syncthreads();

        float acc = 0.f, sq = 0.f;
        if (tid < FCONV) {
            int cp = tid >> 4;
            int j  = tid & 15;
            int c = cp / 3, p = cp % 3;
            int g = fg0 + j;

            const float* w; const float* bias; int ksz, pad;
            if (p == 0)      { w = w1; bias = b1; ksz = 3; pad = 1; }
            else if (p == 1) { w = w2; bias = b2; ksz = 5; pad = 2; }
            else             { w = w3; bias = b3; ksz = 9; pad = 4; }

            acc = bias[c];
            int jj0 = j - pad + HALO;
            for (int t = 0; t < ksz; t++)
                acc = fmaf(w[c * ksz + t], sh.f.spos[(jj0 + t) * 9 + cp], acc);

            g_conv[((fb * NG + g) * CH + c) * NP + p] = acc;
            sq = acc * acc;
        }
#pragma unroll
        for (int st = 8; st > 0; st >>= 1) {
            acc += __shfl_down_sync(0xffffffffu, acc, st, 16);
            sq  += __shfl_down_sync(0xffffffffu, sq,  st, 16);
        }
        if (tid < FCONV && (tid & 15) == 0) {
            int cp = tid >> 4;
            g_psum[cp * FTILES + unit] = acc;
            g_psq [cp * FTILES + unit] = sq;
        }
    }

    grid_bar(3u * NBLK);

    // ================= Phase 3: BN finalize + feat + 18->64 linear =================
    if (unit < FTILES) {
        int pos0 = unit * K5P;

        for (int t = tid; t < OC * 18; t += NTHR)
            sh.f.sgw[(t / 18) * 19 + (t % 18)] = gw[t];
        if (tid < OC) sh.f.sgb2[tid] = gb[tid];

        {
            float s = 0.f, q = 0.f;
            int cp = tid >> 4, l = tid & 15;
            if (tid < 144) {
                for (int k = l; k < FTILES; k += 16) {
                    s += g_psum[cp * FTILES + k];
                    q += g_psq [cp * FTILES + k];
                }
            }
#pragma unroll
            for (int st = 8; st > 0; st >>= 1) {
                s += __shfl_down_sync(0xffffffffu, s, st, 16);
                q += __shfl_down_sync(0xffffffffu, q, st, 16);
            }
            if (tid < 144 && l == 0) {
                const float invn = 1.0f / (float)(NB * NG);
                float m   = s * invn;
                float var = q * invn - m * m;
                float rs  = rsqrtf(var + BNEPS);
                int c = cp / 3, p = cp % 3;
                float ga = gamma[p * CH + c];
                float be = beta [p * CH + c];
                sh.f.sA[cp] = rs * ga;
                sh.f.sB[cp] = be - m * rs * ga;
            }
        }
        __syncthreads();

        for (int t = tid; t < K5P * 18; t += NTHR) {
            int pl = t / 18, k = t % 18;
            int pos = pos0 + pl;
            float v;
            if (k < 9) {
                v = out[OFF_H0 + pos * 9 + k];
            } else {
                int cp = k - 9;
                v = fmaf(g_conv[pos * 9 + cp], sh.f.sA[cp], sh.f.sB[cp]);
                out[OFF_NF + pos * 9 + cp] = v;
            }
            sh.f.feat[pl * 18 + k] = v;
        }
        __syncthreads();

        for (int t = tid; t < K5P * OC; t += NTHR) {
            int pl = t / OC, oc = t % OC;
            float a2 = sh.f.sgb2[oc];
#pragma unroll
            for (int f = 0; f < 18; f++)
                a2 = fmaf(sh.f.feat[pl * 18 + f], sh.f.sgw[oc * 19 + f], a2);
            out[(pos0 + pl) * OC + oc] = a2;
        }
    }

    // ---- self-reset of barrier counter for next graph replay ----
    __syncthreads();
    if (tid == 0) {
        __threadfence();
        unsigned e = atomicAdd(&g_exit, 1u);
        if (e == (unsigned)(NBLK - 1)) {
            g_bar  = 0u;
            g_exit = 0u;
            __threadfence();
        }
    }
}

// ---------------- launch ----------------
extern "C" void kernel_launch(void* const* d_in, const int* in_sizes, int n_in,
                              void* d_out, int out_size)
{
    const float* x_c   = (const float*)d_in[0];
    const float* y_c   = (const float*)d_in[1];
    const float* x_g   = (const float*)d_in[2];
    const float* sigma = (const float*)d_in[3];
    const float* mu    = (const float*)d_in[4];
    const float* eps1  = (const float*)d_in[5];
    const float* b_u   = (const float*)d_in[6];
    const float* rw    = (const float*)d_in[7];
    const float* w1    = (const float*)d_in[8];
    const float* b1    = (const float*)d_in[9];
    const float* w2    = (const float*)d_in[10];
    const float* b2    = (const float*)d_in[11];
    const float* w3    = (const float*)d_in[12];
    const float* b3    = (const float*)d_in[13];
    const float* gam   = (const float*)d_in[14];
    const float* bet   = (const float*)d_in[15];
    const float* gw    = (const float*)d_in[16];
    const float* gb    = (const float*)d_in[17];
    float* out = (float*)d_out;

    k_all<<<NBLK, NTHR>>>(x_c, y_c, x_g, sigma, mu, eps1, b_u, rw,
                          w1, b1, w2, b2, w3, b3,
                          gam, bet, gw, gb, out);
}

// round 9
// speedup vs baseline: 1.0074x; 1.0074x over previous
#include <cuda_runtime.h>

// ---------------- problem constants ----------------
#define NB 4
#define NC 512
#define NG 2048
#define CH 3
#define NP 3
#define NBAS 10
#define OC 64
#define EPSF 1e-6f
#define BNEPS 1e-5f
#define LOG2E_F 1.4426950408889634f
#define PI2F 6.283185307179586f
#define INV2PI_F 0.15915494309189535f
#define PI2_D 6.2831853071795864769
#define SQRT_2_OVER_NBAS 0.4472135954999579f

#define ELEMS (NB * NG * CH * NP)  // 73728
#define NBIN 1024
#define RFACT 15.0f                // window radius = 15*scale (> 13.22 ftz-zero bound)

#define SORT_BLKS 96               // 8 blocks per (b,c), 64 elements each
#define BIN_BLKS 12
#define PREP_BLKS (SORT_BLKS + BIN_BLKS)

#define K1_BLOCKS (NB * CH * (NG / 32))   // 768

#define FG 16
#define FBLOCKS (NB * (NG / FG))    // 512
#define FTHREADS 224
#define HALO 4
#define FGH (FG + 2 * HALO)         // 24
#define FCONV (9 * FG)              // 144

#define K5_POS 32
#define K5_BLOCKS ((NB * NG) / K5_POS)  // 256

// output offsets (flattened tuple concat: y_out, n_f, fourier, n_h1, h0_f)
#define OFF_NF  (NB * NG * OC)
#define OFF_FP  (OFF_NF + ELEMS)
#define OFF_NH1 (OFF_FP + ELEMS)
#define OFF_H0  (OFF_NH1 + ELEMS)

// ---------------- scratch (no allocs allowed) ----------------
__device__ float2 g_ctx[NB * CH * NC];   // context (x,y) sorted by x per (b,c)
__device__ float  g_gbx[NB * CH * NG];   // grid x, value-binned per (b,c)
__device__ int    g_gbi[NB * CH * NG];   // original grid index per binned slot
__device__ float  g_ph0[ELEMS];
__device__ float  g_ph1[ELEMS];
__device__ float  g_conv[ELEMS];
__device__ float  g_psum[9 * FBLOCKS];
__device__ float  g_psq [9 * FBLOCKS];

__device__ __forceinline__ float ex2f(float x) {
    float y;
    asm("ex2.approx.ftz.f32 %0, %1;" : "=f"(y) : "f"(x));
    return y;
}

// fp32 Cody-Waite cos reduction (no FP64), abs err ~7e-7 for |arg| up to ~2e5
__device__ __forceinline__ float cos_red(float arg) {
    const float F2PI     = (float)PI2_D;
    const float F2PI_RES = (float)(PI2_D - (double)((float)PI2_D));
    float n = rintf(arg * INV2PI_F);
    float r = fmaf(-n, F2PI, arg);
    r = fmaf(-n, F2PI_RES, r);
    return __cosf(r);
}

// ---------------- kernel 0: prep (rank sort + grid binning), 108 blocks ----------------
// blocks 0..95: O(N^2) rank sort of context per (b,c): 8 blocks/(b,c), 64 elems
// each; warp = (elem-group of 32) x (j-quarter of 128); barrier-light.
// blocks 96..107: value-bin x_g per (b,c). Bin-internal order is nondeterministic
// but provably does not change any output bit (variably-included window edge
// points contribute exactly-zero ftz weights).
__global__ __launch_bounds__(256) void k0_prep(
    const float* __restrict__ x_c, const float* __restrict__ y_c,
    const float* __restrict__ x_g)
{
    __shared__ union {
        struct { unsigned key[NC]; float x[NC]; float y[NC]; int pr[8 * 32]; } srt;
        struct { int hist[NBIN]; int ofs[NBIN]; int ss[256]; } bn;
    } sh;

    int unit = blockIdx.x;
    int tid  = threadIdx.x;

    if (unit < SORT_BLKS) {
        int bc = unit >> 3;
        int part = unit & 7;
        int b = bc / 3, c = bc % 3;
        for (int i = tid; i < NC; i += 256) {
            float xv = x_c[(b * NC + i) * CH + c];
            int f = __float_as_int(xv);
            sh.srt.key[i] = (f < 0) ? ~(unsigned)f : ((unsigned)f | 0x80000000u);
            sh.srt.x[i] = xv;
            sh.srt.y[i] = y_c[(b * NC + i) * CH + c];
        }
        __syncthreads();
        {
            int wq = tid >> 5, lane = tid & 31;
            int grp = wq >> 2, jq = wq & 3;
            int e = part * 64 + grp * 32 + lane;
            unsigned ki = sh.srt.key[e];
            int r = 0;
            int j0 = jq * (NC / 4);
#pragma unroll 8
            for (int j = j0; j < j0 + NC / 4; j++) {
                unsigned kj = sh.srt.key[j];
                r += (kj < ki) ? 1 : 0;
                r += (kj == ki && j < e) ? 1 : 0;
            }
            sh.srt.pr[wq * 32 + lane] = r;
        }
        __syncthreads();
        if (tid < 64) {
            int grp2 = tid >> 5, l2 = tid & 31;
            int rank = sh.srt.pr[(grp2 * 4 + 0) * 32 + l2]
                     + sh.srt.pr[(grp2 * 4 + 1) * 32 + l2]
                     + sh.srt.pr[(grp2 * 4 + 2) * 32 + l2]
                     + sh.srt.pr[(grp2 * 4 + 3) * 32 + l2];
            int e2 = part * 64 + tid;
            g_ctx[bc * NC + rank] = make_float2(sh.srt.x[e2], sh.srt.y[e2]);
        }
    } else {
        int u = unit - SORT_BLKS;
        int b = u / 3, c = u % 3;
        for (int i = tid; i < NBIN; i += 256) sh.bn.hist[i] = 0;
        __syncthreads();
        for (int i = tid; i < NG; i += 256) {
            float xv = x_g[(b * NG + i) * CH + c];
            int bin = (int)((xv + 5.0f) * (NBIN / 10.0f));
            bin = min(max(bin, 0), NBIN - 1);
            atomicAdd(&sh.bn.hist[bin], 1);
        }
        __syncthreads();
        int b4 = 4 * tid;
        int h0v = sh.bn.hist[b4], h1v = sh.bn.hist[b4 + 1];
        int h2v = sh.bn.hist[b4 + 2], h3v = sh.bn.hist[b4 + 3];
        sh.bn.ss[tid] = h0v + h1v + h2v + h3v;
        __syncthreads();
        for (int d = 1; d < 256; d <<= 1) {
            int v = sh.bn.ss[tid];
            int w2 = (tid >= d) ? sh.bn.ss[tid - d] : 0;
            __syncthreads();
            sh.bn.ss[tid] = v + w2;
            __syncthreads();
        }
        int excl = tid ? sh.bn.ss[tid - 1] : 0;
        sh.bn.ofs[b4]     = excl;
        sh.bn.ofs[b4 + 1] = excl + h0v;
        sh.bn.ofs[b4 + 2] = excl + h0v + h1v;
        sh.bn.ofs[b4 + 3] = excl + h0v + h1v + h2v;
        __syncthreads();
        for (int i = tid; i < NG; i += 256) {
            float xv = x_g[(b * NG + i) * CH + c];
            int bin = (int)((xv + 5.0f) * (NBIN / 10.0f));
            bin = min(max(bin, 0), NBIN - 1);
            int p = atomicAdd(&sh.bn.ofs[bin], 1);
            g_gbx[(b * CH + c) * NG + p] = xv;
            g_gbi[(b * CH + c) * NG + p] = i;
        }
    }
}

// ---------------- kernel 1: windowed RBF sums ----------------
// 768 blocks x 256 threads. Block = (b, c, tile of 32 value-adjacent grid pts).
// 8 warps cover fixed context chunks {w, w+8, w+16, w+24} (16 pts each),
// intersected with the warp's per-p window [lo-15s, hi+15s]. Fixed chunk
// boundaries + fixed combine order => bit-deterministic sums.
__global__ __launch_bounds__(256) void k1_rbf(const float* __restrict__ sigma)
{
    __shared__ float2 sctx[NC];
    __shared__ float  sxv[32];
    __shared__ int    sgi[32];
    __shared__ float  sacc[8 * 6 * 32];

    int unit = blockIdx.x;
    int gt = unit % (NG / 32);
    int c  = (unit / (NG / 32)) % CH;
    int b  = unit / ((NG / 32) * CH);
    int tid = threadIdx.x;
    int lane = tid & 31, w = tid >> 5;

    const float2* ctx = g_ctx + (b * CH + c) * NC;
    for (int i = tid; i < NC; i += 256) sctx[i] = ctx[i];
    if (tid < 32) {
        sxv[tid] = g_gbx[(b * CH + c) * NG + gt * 32 + tid];
        sgi[tid] = g_gbi[(b * CH + c) * NG + gt * 32 + tid];
    }
    __syncthreads();

    float xg = sxv[lane];
    float lo = xg, hi = xg;
#pragma unroll
    for (int st = 16; st; st >>= 1) {
        lo = fminf(lo, __shfl_xor_sync(0xffffffffu, lo, st));
        hi = fmaxf(hi, __shfl_xor_sync(0xffffffffu, hi, st));
    }

    float ks[3], rr[3];
#pragma unroll
    for (int p = 0; p < 3; p++) {
        float s = expf(sigma[p]) + EPSF;
        ks[p] = -0.5f * LOG2E_F / (s * s);
        rr[p] = RFACT * s;
    }

#pragma unroll
    for (int p = 0; p < 3; p++) {
        float vlo = lo - rr[p], vhi = hi + rr[p];
        int i0, i1;
        { int l = 0, h = NC; while (l < h) { int m = (l + h) >> 1; if (sctx[m].x < vlo) l = m + 1; else h = m; } i0 = l; }
        { int l = 0, h = NC; while (l < h) { int m = (l + h) >> 1; if (sctx[m].x < vhi) l = m + 1; else h = m; } i1 = l; }
        float kp = ks[p];
        float a0 = 0.f, a1 = 0.f;
#pragma unroll
        for (int cc = 0; cc < 4; cc++) {
            int ci = w + cc * 8;
            int a  = max(i0, ci * 16);
            int bb = min(i1, ci * 16 + 16);
#pragma unroll 2
            for (int i = a; i < bb; i++) {
                float2 cy = sctx[i];
                float d = xg - cy.x;
                float wv = ex2f(d * d * kp);
                a0 += wv;
                a1 = fmaf(wv, cy.y, a1);
            }
        }
        sacc[(w * 6 + p * 2 + 0) * 32 + lane] = a0;
        sacc[(w * 6 + p * 2 + 1) * 32 + lane] = a1;
    }
    __syncthreads();

    if (tid < 192) {
        int j = tid >> 5;
        int l = tid & 31;
        float v = 0.f;
#pragma unroll
        for (int s = 0; s < 8; s++) v += sacc[(s * 6 + j) * 32 + l];
        int p = j >> 1;
        int base = ((b * NG + sgi[l]) * CH + c) * NP + p;
        if ((j & 1) == 0) g_ph0[base] = v;
        else              g_ph1[base] = v;
    }
}

// ---------------- kernel F: combine + Fourier + depthwise conv + BN partials ----------------
// 512 blocks x 224 threads.
__global__ __launch_bounds__(FTHREADS) void kF_fused(
    const float* __restrict__ x_g, const float* __restrict__ sigma,
    const float* __restrict__ mu,  const float* __restrict__ eps1,
    const float* __restrict__ b_u, const float* __restrict__ rw,
    const float* __restrict__ w1, const float* __restrict__ b1,
    const float* __restrict__ w2, const float* __restrict__ b2,
    const float* __restrict__ w3, const float* __restrict__ b3,
    float* __restrict__ out)
{
    __shared__ float spos[FGH * 9];
    __shared__ float ssw[NBAS * 3];
    __shared__ float ssb[NBAS * 3];
    __shared__ float srw[NBAS];

    int tid = threadIdx.x;
    int b   = blockIdx.x / (NG / FG);
    int gt  = blockIdx.x % (NG / FG);
    int g0  = gt * FG;

    if (tid < NBAS * 3) {
        int k = tid / 3, p = tid % 3;
        float wmu  = expf(mu[p]);
        float wstd = 1.0f / (expf(sigma[p]) + EPSF);
        float e = eps1[(b * NBAS + k) * NP + p];
        float u = b_u [(b * NBAS + k) * NP + p];
        ssw[tid] = __fadd_rn(wmu, __fmul_rn(wstd, e));
        ssb[tid] = __fmul_rn(PI2F, u);
    }
    if (tid < NBAS) srw[tid] = rw[tid];
    __syncthreads();

    // Phase 1: pos = n_h1 + fourier, one element per thread
    if (tid < FGH * 9) {
        int jj = tid / 9;
        int cp = tid % 9;
        int c = cp / 3, p = cp % 3;
        int g = g0 - HALO + jj;
        float pos = 0.f;
        if (g >= 0 && g < NG) {
            int idx = ((b * NG + g) * CH + c) * NP + p;
            float h0 = g_ph0[idx];
            float h1 = g_ph1[idx];
            float nh1 = h1 / (h0 + EPSF);

            float xg = x_g[(b * NG + g) * CH + c];
            float acc = 0.f;
#pragma unroll
            for (int k = 0; k < NBAS; k++) {
                float arg = __fadd_rn(__fmul_rn(ssw[k * 3 + p], xg), ssb[k * 3 + p]);
                acc = __fadd_rn(acc, __fmul_rn(srw[k], cos_red(arg)));
            }
            float fp = SQRT_2_OVER_NBAS * acc;
            pos = nh1 + fp;

            if (jj >= HALO && jj < HALO + FG) {
                out[OFF_NH1 + idx] = nh1;
                out[OFF_FP  + idx] = fp;
                out[OFF_H0  + idx] = h0;
            }
        }
        spos[tid] = pos;
    }
    __syncthreads();

    // Phase 2: depthwise conv + per-cp partial stats
    float acc = 0.f, sq = 0.f;
    if (tid < FCONV) {
        int cp = tid >> 4;
        int j  = tid & 15;
        int c = cp / 3, p = cp % 3;
        int g = g0 + j;

        const float* w; const float* bias; int ksz, pad;
        if (p == 0)      { w = w1; bias = b1; ksz = 3; pad = 1; }
        else if (p == 1) { w = w2; bias = b2; ksz = 5; pad = 2; }
        else             { w = w3; bias = b3; ksz = 9; pad = 4; }

        acc = bias[c];
        int jj0 = j - pad + HALO;
        for (int t = 0; t < ksz; t++)
            acc = fmaf(w[c * ksz + t], spos[(jj0 + t) * 9 + cp], acc);

        g_conv[((b * NG + g) * CH + c) * NP + p] = acc;
        sq = acc * acc;
    }
#pragma unroll
    for (int st = 8; st > 0; st >>= 1) {
        acc += __shfl_down_sync(0xffffffffu, acc, st, 16);
        sq  += __shfl_down_sync(0xffffffffu, sq,  st, 16);
    }
    if (tid < FCONV && (tid & 15) == 0) {
        int cp = tid >> 4;
        g_psum[cp * FBLOCKS + blockIdx.x] = acc;
        g_psq [cp * FBLOCKS + blockIdx.x] = sq;
    }
}

// ---------------- kernel 5: BN finalize + apply + n_f + final linear (18 -> 64) ----------------
#define GW_STRIDE 19
__global__ __launch_bounds__(256) void k5_final(
    const float* __restrict__ gamma, const float* __restrict__ beta,
    const float* __restrict__ gw,    const float* __restrict__ gb,
    float* __restrict__ out)
{
    __shared__ float sgw[OC * GW_STRIDE];
    __shared__ float sgb[OC];
    __shared__ float sA[9], sB[9];
    __shared__ float feat[K5_POS * 18];

    int tid = threadIdx.x;
    int pos0 = blockIdx.x * K5_POS;

    for (int t = tid; t < OC * 18; t += 256)
        sgw[(t / 18) * GW_STRIDE + (t % 18)] = gw[t];
    if (tid < OC) sgb[tid] = gb[tid];

    {
        float s = 0.f, q = 0.f;
        int cp = tid >> 4, l = tid & 15;
        if (tid < 144) {
            for (int k = l; k < FBLOCKS; k += 16) {
                s += g_psum[cp * FBLOCKS + k];
                q += g_psq [cp * FBLOCKS + k];
            }
        }
#pragma unroll
        for (int st = 8; st > 0; st >>= 1) {
            s += __shfl_down_sync(0xffffffffu, s, st, 16);
            q += __shfl_down_sync(0xffffffffu, q, st, 16);
        }
        if (tid < 144 && l == 0) {
            const float invn = 1.0f / (float)(NB * NG);
            float m   = s * invn;
            float var = q * invn - m * m;
            float rs  = rsqrtf(var + BNEPS);
            int c = cp / 3, p = cp % 3;
            float ga = gamma[p * CH + c];
            float be = beta [p * CH + c];
            sA[cp] = rs * ga;
            sB[cp] = be - m * rs * ga;
        }
    }
    __syncthreads();

    for (int t = tid; t < K5_POS * 18; t += 256) {
        int pl = t / 18, k = t % 18;
        int pos = pos0 + pl;
        float v;
        if (k < 9) {
            v = out[OFF_H0 + pos * 9 + k];
        } else {
            int cp = k - 9;
            v = fmaf(g_conv[pos * 9 + cp], sA[cp], sB[cp]);
            out[OFF_NF + pos * 9 + cp] = v;
        }
        feat[pl * 18 + k] = v;
    }
    __syncthreads();

    int oc = tid % OC;
    int pp = tid / OC;
#pragma unroll
    for (int i = 0; i < K5_POS / 4; i++) {
        int pl = pp * (K5_POS / 4) + i;
        float acc = sgb[oc];
#pragma unroll
        for (int f = 0; f < 18; f++)
            acc = fmaf(feat[pl * 18 + f], sgw[oc * GW_STRIDE + f], acc);
        out[(pos0 + pl) * OC + oc] = acc;
    }
}

// ---------------- launch ----------------
extern "C" void kernel_launch(void* const* d_in, const int* in_sizes, int n_in,
                              void* d_out, int out_size)
{
    const float* x_c   = (const float*)d_in[0];
    const float* y_c   = (const float*)d_in[1];
    const float* x_g   = (const float*)d_in[2];
    const float* sigma = (const float*)d_in[3];
    const float* mu    = (const float*)d_in[4];
    const float* eps1  = (const float*)d_in[5];
    const float* b_u   = (const float*)d_in[6];
    const float* rw    = (const float*)d_in[7];
    const float* w1    = (const float*)d_in[8];
    const float* b1    = (const float*)d_in[9];
    const float* w2    = (const float*)d_in[10];
    const float* b2    = (const float*)d_in[11];
    const float* w3    = (const float*)d_in[12];
    const float* b3    = (const float*)d_in[13];
    const float* gam   = (const float*)d_in[14];
    const float* bet   = (const float*)d_in[15];
    const float* gw    = (const float*)d_in[16];
    const float* gb    = (const float*)d_in[17];
    float* out = (float*)d_out;

    k0_prep<<<PREP_BLKS, 256>>>(x_c, y_c, x_g);
    k1_rbf<<<K1_BLOCKS, 256>>>(sigma);
    kF_fused<<<FBLOCKS, FTHREADS>>>(x_g, sigma, mu, eps1, b_u, rw,
                                    w1, b1, w2, b2, w3, b3, out);
    k5_final<<<K5_BLOCKS, 256>>>(gam, bet, gw, gb, out);
}

// round 11
// speedup vs baseline: 1.4718x; 1.4610x over previous
#include <cuda_runtime.h>

// ---------------- problem constants ----------------
#define NB 4
#define NC 512
#define NG 2048
#define CH 3
#define NP 3
#define NBAS 10
#define OC 64
#define EPSF 1e-6f
#define BNEPS 1e-5f
#define LOG2E_F 1.4426950408889634f
#define PI2F 6.283185307179586f
#define INV2PI_F 0.15915494309189535f
#define PI2_D 6.2831853071795864769
#define SQRT_2_OVER_NBAS 0.4472135954999579f

#define SPLIT 8
#define NCHUNK (NC / SPLIT)   // 64
#define TILE_G 64
#define GTILES (NG / TILE_G)  // 32

#define ELEMS (NB * NG * CH * NP)  // 73728

// fused combine/conv kernel tiling
#define FG 16
#define FBLOCKS (NB * (NG / FG))    // 512
#define FTHREADS 224
#define HALO 4
#define FGH (FG + 2 * HALO)         // 24
#define FCONV (9 * FG)              // 144

// final kernel tiling
#define K5_POS 32
#define K5_BLOCKS ((NB * NG) / K5_POS)  // 256

// output offsets (flattened tuple concat: y_out, n_f, fourier, n_h1, h0_f)
#define OFF_NF  (NB * NG * OC)        // 524288
#define OFF_FP  (OFF_NF + ELEMS)      // 598016
#define OFF_NH1 (OFF_FP + ELEMS)      // 671744
#define OFF_H0  (OFF_NH1 + ELEMS)     // 745472

// ---------------- scratch (no allocs allowed) ----------------
__device__ float g_ph0[SPLIT * ELEMS];
__device__ float g_ph1[SPLIT * ELEMS];
__device__ float g_conv[ELEMS];             // conv output (pre-BN)
__device__ float g_psum[9 * FBLOCKS];       // per-cp per-block partial sums
__device__ float g_psq [9 * FBLOCKS];       // per-cp per-block partial sum-squares
__device__ float g_bnA[9];                  // folded BN: v*A + B
__device__ float g_bnB[9];

__device__ __forceinline__ float ex2f(float x) {
    float y;
    asm("ex2.approx.ftz.f32 %0, %1;" : "=f"(y) : "f"(x));
    return y;
}

// ---------------- kernel 1: RBF pairwise partial sums (lean scalar, dense) ----------------
// grid: NB * GTILES * SPLIT = 1024 blocks, block: 192 threads (6 warps).
// warp w: c = w % 3 (uniform), g = gt*64 + (w/3)*32 + lane.
// Scalar math, float2 shared loads, 12 even/odd accumulators. MUFU-bound (measured 14.8us).
__global__ __launch_bounds__(CH * TILE_G) void k1_rbf(
    const float* __restrict__ x_c, const float* __restrict__ y_c,
    const float* __restrict__ x_g, const float* __restrict__ sigma)
{
    __shared__ __align__(8) float sxp[NCHUNK * CH];  // pair-interleaved x
    __shared__ __align__(8) float syp[NCHUNK * CH];

    int unit = blockIdx.x;
    int s  = unit % SPLIT;
    int gt = (unit / SPLIT) % GTILES;
    int b  = unit / (SPLIT * GTILES);

    int lane = threadIdx.x & 31;
    int w    = threadIdx.x >> 5;       // 0..5
    int c    = w % 3;                  // uniform per warp
    int g    = gt * TILE_G + (w / 3) * 32 + lane;
    int n0   = s * NCHUNK;

    const float* xb = x_c + (b * NC + n0) * CH;
    const float* yb = y_c + (b * NC + n0) * CH;
    for (int i = threadIdx.x; i < NCHUNK * CH; i += blockDim.x) {
        int n = i / CH, cc = i % CH;
        int slot = ((n >> 1) * CH + cc) * 2 + (n & 1);
        sxp[slot] = xb[i];
        syp[slot] = yb[i];
    }
    __syncthreads();

    float xg = x_g[(b * NG + g) * CH + c];

    float s0 = expf(sigma[0]) + EPSF;
    float s1 = expf(sigma[1]) + EPSF;
    float s2 = expf(sigma[2]) + EPSF;
    float k0 = -0.5f * LOG2E_F / (s0 * s0);
    float k1 = -0.5f * LOG2E_F / (s1 * s1);
    float k2 = -0.5f * LOG2E_F / (s2 * s2);

    float h00e = 0.f, h01e = 0.f, h02e = 0.f;
    float h00o = 0.f, h01o = 0.f, h02o = 0.f;
    float h10e = 0.f, h11e = 0.f, h12e = 0.f;
    float h10o = 0.f, h11o = 0.f, h12o = 0.f;

    const float2* sx2 = (const float2*)sxp;
    const float2* sy2 = (const float2*)syp;

#pragma unroll 8
    for (int n2 = 0; n2 < NCHUNK / 2; n2++) {
        float2 xv = sx2[n2 * CH + c];   // broadcast LDS.64 (warp-uniform addr)
        float2 yv = sy2[n2 * CH + c];
        float d0 = xg - xv.x;
        float d1 = xg - xv.y;
        float t0 = d0 * d0;
        float t1 = d1 * d1;
        float wv;
        wv = ex2f(t0 * k0); h00e += wv; h10e = fmaf(wv, yv.x, h10e);
        wv = ex2f(t1 * k0); h00o += wv; h10o = fmaf(wv, yv.y, h10o);
        wv = ex2f(t0 * k1); h01e += wv; h11e = fmaf(wv, yv.x, h11e);
        wv = ex2f(t1 * k1); h01o += wv; h11o = fmaf(wv, yv.y, h11o);
        wv = ex2f(t0 * k2); h02e += wv; h12e = fmaf(wv, yv.x, h12e);
        wv = ex2f(t1 * k2); h02o += wv; h12o = fmaf(wv, yv.y, h12o);
    }

    int base = ((b * NG + g) * CH + c) * NP;
    int off  = s * ELEMS + base;
    g_ph0[off + 0] = h00e + h00o;
    g_ph0[off + 1] = h01e + h01o;
    g_ph0[off + 2] = h02e + h02o;
    g_ph1[off + 0] = h10e + h10o;
    g_ph1[off + 1] = h11e + h11o;
    g_ph1[off + 2] = h12e + h12o;
}

// fp32 Cody-Waite cos for args up to ~2e5: two single-rounding FMAs remove
// n*2pi, then hardware cos on |r| <= pi+eps. abs err ~7e-7, no FP64.
__device__ __forceinline__ float cos_red(float arg) {
    const float F2PI     = (float)PI2_D;
    const float F2PI_RES = (float)(PI2_D - (double)((float)PI2_D));
    float n = rintf(arg * INV2PI_F);
    float r = fmaf(-n, F2PI, arg);
    r = fmaf(-n, F2PI_RES, r);
    return __cosf(r);
}

// ---------------- kernel F: combine + Fourier prior + depthwise conv + BN partials ----------------
// grid: 512 blocks (b x g-tile of 16), 224 threads.
__global__ __launch_bounds__(FTHREADS) void kF_fused(
    const float* __restrict__ x_g, const float* __restrict__ sigma,
    const float* __restrict__ mu,  const float* __restrict__ eps1,
    const float* __restrict__ b_u, const float* __restrict__ rw,
    const float* __restrict__ w1, const float* __restrict__ b1,
    const float* __restrict__ w2, const float* __restrict__ b2,
    const float* __restrict__ w3, const float* __restrict__ b3,
    float* __restrict__ out)
{
    __shared__ float spos[FGH * 9];       // 216
    __shared__ float ssw[NBAS * 3];
    __shared__ float ssb[NBAS * 3];
    __shared__ float srw[NBAS];

    int tid = threadIdx.x;
    int b   = blockIdx.x / (NG / FG);
    int gt  = blockIdx.x % (NG / FG);
    int g0  = gt * FG;

    if (tid < NBAS * 3) {
        int k = tid / 3, p = tid % 3;
        float wmu  = expf(mu[p]);
        float wstd = 1.0f / (expf(sigma[p]) + EPSF);
        float e = eps1[(b * NBAS + k) * NP + p];
        float u = b_u [(b * NBAS + k) * NP + p];
        ssw[tid] = __fadd_rn(wmu, __fmul_rn(wstd, e));
        ssb[tid] = __fmul_rn(PI2F, u);
    }
    if (tid < NBAS) srw[tid] = rw[tid];
    __syncthreads();

    // Phase 1: pos = n_h1 + fourier, one element per thread
    if (tid < FGH * 9) {
        int jj = tid / 9;
        int cp = tid % 9;
        int c = cp / 3, p = cp % 3;
        int g = g0 - HALO + jj;
        float pos = 0.f;
        if (g >= 0 && g < NG) {
            int idx = ((b * NG + g) * CH + c) * NP + p;
            float h0 = 0.f, h1 = 0.f;
#pragma unroll
            for (int s = 0; s < SPLIT; s++) {
                h0 += g_ph0[s * ELEMS + idx];
                h1 += g_ph1[s * ELEMS + idx];
            }
            float nh1 = h1 / (h0 + EPSF);

            float xg = x_g[(b * NG + g) * CH + c];
            float acc = 0.f;
#pragma unroll
            for (int k = 0; k < NBAS; k++) {
                float arg = __fadd_rn(__fmul_rn(ssw[k * 3 + p], xg), ssb[k * 3 + p]);
                acc = __fadd_rn(acc, __fmul_rn(srw[k], cos_red(arg)));
            }
            float fp = SQRT_2_OVER_NBAS * acc;
            pos = nh1 + fp;

            if (jj >= HALO && jj < HALO + FG) {
                out[OFF_NH1 + idx] = nh1;
                out[OFF_FP  + idx] = fp;
                out[OFF_H0  + idx] = h0;
            }
        }
        spos[tid] = pos;
    }
    __syncthreads();

    // Phase 2: depthwise conv + per-cp partial stats
    float acc = 0.f, sq = 0.f;
    if (tid < FCONV) {
        int cp = tid >> 4;        // 0..8
        int j  = tid & 15;        // 0..15
        int c = cp / 3, p = cp % 3;
        int g = g0 + j;

        const float* w; const float* bias; int ksz, pad;
        if (p == 0)      { w = w1; bias = b1; ksz = 3; pad = 1; }
        else if (p == 1) { w = w2; bias = b2; ksz = 5; pad = 2; }
        else             { w = w3; bias = b3; ksz = 9; pad = 4; }

        acc = bias[c];
        int jj0 = j - pad + HALO;
        for (int t = 0; t < ksz; t++)
            acc = fmaf(w[c * ksz + t], spos[(jj0 + t) * 9 + cp], acc);

        g_conv[((b * NG + g) * CH + c) * NP + p] = acc;
        sq = acc * acc;
    }
    // width-16 segmented shuffle reduce
#pragma unroll
    for (int st = 8; st > 0; st >>= 1) {
        acc += __shfl_down_sync(0xffffffffu, acc, st, 16);
        sq  += __shfl_down_sync(0xffffffffu, sq,  st, 16);
    }
    if (tid < FCONV && (tid & 15) == 0) {
        int cp = tid >> 4;
        g_psum[cp * FBLOCKS + blockIdx.x] = acc;
        g_psq [cp * FBLOCKS + blockIdx.x] = sq;
    }
}

// ---------------- kernel 4b: BN finalize (1 block, 9 warps) ----------------
// Warp w handles cp=w: 16 fully-unrolled strided loads per lane (high MLP),
// width-32 shuffle reduce, fold gamma/beta -> g_bnA/g_bnB.
__global__ __launch_bounds__(288) void k4b_bnfin(
    const float* __restrict__ gamma, const float* __restrict__ beta)
{
    int w    = threadIdx.x >> 5;   // 0..8 == cp
    int lane = threadIdx.x & 31;

    float s = 0.f, q = 0.f;
#pragma unroll
    for (int i = 0; i < FBLOCKS / 32; i++) {
        int k = lane + i * 32;
        s += g_psum[w * FBLOCKS + k];
        q += g_psq [w * FBLOCKS + k];
    }
#pragma unroll
    for (int st = 16; st > 0; st >>= 1) {
        s += __shfl_down_sync(0xffffffffu, s, st);
        q += __shfl_down_sync(0xffffffffu, q, st);
    }
    if (lane == 0) {
        const float invn = 1.0f / (float)(NB * NG);
        float m   = s * invn;
        float var = q * invn - m * m;
        float rs  = rsqrtf(var + BNEPS);
        int c = w / 3, p = w % 3;
        float ga = gamma[p * CH + c];
        float be = beta [p * CH + c];
        g_bnA[w] = rs * ga;
        g_bnB[w] = be - m * rs * ga;
    }
}

// ---------------- kernel 5: BN apply + n_f + final linear (18 -> 64) ----------------
// 256 blocks x 256 threads, 32 positions/block. BN constants pre-folded by k4b,
// so the critical path is just stage-weights -> feat -> GEMM.
#define GW_STRIDE 19
__global__ __launch_bounds__(256) void k5_final(
    const float* __restrict__ gw, const float* __restrict__ gb,
    float* __restrict__ out)
{
    __shared__ float sgw[OC * GW_STRIDE];
    __shared__ float sgb[OC];
    __shared__ float sA[9], sB[9];
    __shared__ float feat[K5_POS * 18];

    int tid = threadIdx.x;
    int pos0 = blockIdx.x * K5_POS;

    if (tid < 9) {
        sA[tid] = g_bnA[tid];
        sB[tid] = g_bnB[tid];
    }
#pragma unroll
    for (int t = tid; t < OC * 18; t += 256)
        sgw[(t / 18) * GW_STRIDE + (t % 18)] = gw[t];
    if (tid < OC) sgb[tid] = gb[tid];
    __syncthreads();

    // build feature tile: [pos][0..8]=h0_f, [pos][9..17]=n_f (BN applied)
#pragma unroll
    for (int t = tid; t < K5_POS * 18; t += 256) {
        int pl = t / 18, k = t % 18;
        int pos = pos0 + pl;
        float v;
        if (k < 9) {
            v = out[OFF_H0 + pos * 9 + k];
        } else {
            int cp = k - 9;
            v = fmaf(g_conv[pos * 9 + cp], sA[cp], sB[cp]);
            out[OFF_NF + pos * 9 + cp] = v;
        }
        feat[pl * 18 + k] = v;
    }
    __syncthreads();

    int oc = tid % OC;
    int pp = tid / OC;
#pragma unroll
    for (int i = 0; i < K5_POS / 4; i++) {
        int pl = pp * (K5_POS / 4) + i;
        float acc = sgb[oc];
#pragma unroll
        for (int f = 0; f < 18; f++)
            acc = fmaf(feat[pl * 18 + f], sgw[oc * GW_STRIDE + f], acc);
        out[(pos0 + pl) * OC + oc] = acc;
    }
}

// ---------------- launch ----------------
extern "C" void kernel_launch(void* const* d_in, const int* in_sizes, int n_in,
                              void* d_out, int out_size)
{
    const float* x_c   = (const float*)d_in[0];
    const float* y_c   = (const float*)d_in[1];
    const float* x_g   = (const float*)d_in[2];
    const float* sigma = (const float*)d_in[3];
    const float* mu    = (const float*)d_in[4];
    const float* eps1  = (const float*)d_in[5];
    const float* b_u   = (const float*)d_in[6];
    const float* rw    = (const float*)d_in[7];
    const float* w1    = (const float*)d_in[8];
    const float* b1    = (const float*)d_in[9];
    const float* w2    = (const float*)d_in[10];
    const float* b2    = (const float*)d_in[11];
    const float* w3    = (const float*)d_in[12];
    const float* b3    = (const float*)d_in[13];
    const float* gam   = (const float*)d_in[14];
    const float* bet   = (const float*)d_in[15];
    const float* gw    = (const float*)d_in[16];
    const float* gb    = (const float*)d_in[17];
    float* out = (float*)d_out;

    k1_rbf<<<NB * GTILES * SPLIT, CH * TILE_G>>>(x_c, y_c, x_g, sigma);
    kF_fused<<<FBLOCKS, FTHREADS>>>(x_g, sigma, mu, eps1, b_u, rw,
                                    w1, b1, w2, b2, w3, b3, out);
    k4b_bnfin<<<1, 288>>>(gam, bet);
    k5_final<<<K5_BLOCKS, 256>>>(gw, gb, out);
}